// round 10
// baseline (speedup 1.0000x reference)
#include <cuda_runtime.h>
#include <cstdint>

#define NUM_ANCHORS 145152
#define NUM_CH 85
#define INV_IMG (1.0f / 1536.0f)
#define ROWS_PER_TILE 16
#define WARPS_PER_BLOCK 6
#define THREADS (WARPS_PER_BLOCK * 32)
#define DEPTH 3
#define NUM_TILES (NUM_ANCHORS / ROWS_PER_TILE)        // 9072
#define TILE_FLOATS (ROWS_PER_TILE * NUM_CH)           // 1360
#define TILE_F4 (TILE_FLOATS / 4)                      // 340
#define BUF_FLOATS (DEPTH * TILE_FLOATS)               // per-warp ring
#define SMEM_BYTES (WARPS_PER_BLOCK * BUF_FLOATS * 4)  // 97920 B

// d_out layout (fp32), reference tuple order, flattened:
//   [0 .. 4N)    bboxes     (N,4) = x0, y0, x1, y1
//   [4N .. 5N)   scores     (N,)
//   [5N .. 6N)   class_pred (N,)  (as float)
//   [6N .. 12N)  detections (N,6) = x0, y0, x1, y1, conf, cls

__device__ __forceinline__ unsigned smem_u32(const void* p) {
    unsigned a;
    asm("{ .reg .u64 t; cvta.to.shared.u64 t, %1; cvt.u32.u64 %0, t; }"
        : "=r"(a) : "l"(p));
    return a;
}

__device__ __forceinline__ void cp_async16(unsigned dst, const void* src) {
    asm volatile("cp.async.cg.shared.global [%0], [%1], 16;"
                 :: "r"(dst), "l"(src));
}

// Stage one 16-row tile (5440 B = 340 float4, contiguous) per warp.
// Caller commits the group.
__device__ __forceinline__ void issue_tile_load(unsigned dst0,
                                                const float* __restrict__ pred,
                                                int tile, int lane)
{
    const float4* src = (const float4*)(pred + (long long)tile * TILE_FLOATS);
    #pragma unroll
    for (int j = 0; j < TILE_F4 / 32; ++j)           // 10 full rounds
        cp_async16(dst0 + (lane + j * 32) * 16, src + lane + j * 32);
    if (lane < TILE_F4 - (TILE_F4 / 32) * 32)        // remainder: 20 lanes
        cp_async16(dst0 + (lane + (TILE_F4 / 32) * 32) * 16,
                   src + lane + (TILE_F4 / 32) * 32);
}

__device__ __forceinline__ void compute_tile(const float* __restrict__ s_base,
                                             float* __restrict__ out,
                                             int tile, int lane)
{
    const unsigned FULL = 0xffffffffu;
    const int row  = lane >> 1;               // 0..15
    const int half = lane & 1;
    const float* s = s_base + row * NUM_CH;   // both pair lanes: SAME row
    const int anchor = tile * ROWS_PER_TILE + row;

    // Header (both lanes read identical values from the shared row).
    float cx  = s[0];
    float cy  = s[1];
    float w   = s[2];
    float h   = s[3];
    float obj = s[4];

    // Lane covers 40 channels: even -> ch 0..39, odd -> ch 40..79.
    const int base = 40 * half;
    const float* cs = s + 5 + base;

    float v[40];
    #pragma unroll
    for (int k = 0; k < 40; ++k) v[k] = cs[k];

    // Tournament tree, depth 6. Left operand always lower channel index,
    // so '>=' gives exact lowest-index-wins tie-break.
    float tv[20]; int ti[20];
    #pragma unroll
    for (int k = 0; k < 20; ++k) {
        bool p = v[2*k] >= v[2*k+1];
        tv[k] = p ? v[2*k] : v[2*k+1];
        ti[k] = p ? 2*k : 2*k+1;
    }
    #pragma unroll
    for (int k = 0; k < 10; ++k) {
        bool p = tv[2*k] >= tv[2*k+1];
        tv[k] = p ? tv[2*k] : tv[2*k+1];
        ti[k] = p ? ti[2*k] : ti[2*k+1];
    }
    #pragma unroll
    for (int k = 0; k < 5; ++k) {
        bool p = tv[2*k] >= tv[2*k+1];
        tv[k] = p ? tv[2*k] : tv[2*k+1];
        ti[k] = p ? ti[2*k] : ti[2*k+1];
    }
    bool p0 = tv[0] >= tv[1]; float a = p0 ? tv[0] : tv[1]; int ai = p0 ? ti[0] : ti[1];
    bool p1 = tv[2] >= tv[3]; float b = p1 ? tv[2] : tv[3]; int bj = p1 ? ti[2] : ti[3];
    bool p2 = a >= b;         float c = p2 ? a : b;         int ci = p2 ? ai : bj;
    bool p3 = c >= tv[4];     float bv = p3 ? c : tv[4];    int bl = p3 ? ci : ti[4];
    int bidx = base + bl;     // global channel index 0..79

    // Combine the two lane halves (lowest index wins ties).
    float ov = __shfl_xor_sync(FULL, bv, 1);
    int   oi = __shfl_xor_sync(FULL, bidx, 1);
    if (ov > bv || (ov == bv && oi < bidx)) { bv = ov; bidx = oi; }

    float bx = cx * INV_IMG;
    float by = cy * INV_IMG;
    float bw = w  * INV_IMG;
    float bh = h  * INV_IMG;
    float x0 = bx - bw * 0.5f;
    float y0 = by - bh * 0.5f;
    float x1 = bx + bw * 0.5f;
    float y1 = by + bh * 0.5f;

    float conf  = bv;
    float clsf  = (float)bidx;
    float score = obj * conf;

    float* out_sc  = out + (long long)NUM_ANCHORS * 4;
    float* out_cls = out + (long long)NUM_ANCHORS * 5;
    float* out_det = out + (long long)NUM_ANCHORS * 6;

    if (half == 0) {
        ((float4*)out)[anchor] = make_float4(x0, y0, x1, y1);
        out_sc[anchor]  = score;
        out_cls[anchor] = clsf;
    } else {
        float2* det = (float2*)(out_det + (long long)anchor * 6);
        det[0] = make_float2(x0, y0);
        det[1] = make_float2(x1, y1);
        det[2] = make_float2(conf, clsf);
    }
}

__global__ __launch_bounds__(THREADS)
void yolo_decode_kernel(const float* __restrict__ pred,
                        float* __restrict__ out,
                        int n_warps_total)
{
    extern __shared__ float smem[];

    const int warp = threadIdx.x >> 5;
    const int lane = threadIdx.x & 31;
    const int wgid = blockIdx.x * WARPS_PER_BLOCK + warp;

    float* wbase = smem + warp * BUF_FLOATS;
    unsigned dsts[DEPTH];
    #pragma unroll
    for (int k = 0; k < DEPTH; ++k)
        dsts[k] = smem_u32(wbase + k * TILE_FLOATS);

    // ---- Prologue: put DEPTH-1 tile loads in flight ----
    #pragma unroll
    for (int k = 0; k < DEPTH - 1; ++k) {
        int t = wgid + k * n_warps_total;
        if (t < NUM_TILES)
            issue_tile_load(dsts[k], pred, t, lane);
        asm volatile("cp.async.commit_group;");
    }

    // ---- Steady state: DEPTH-1 groups always pending during compute ----
    int slot = 0;
    for (int t = wgid; t < NUM_TILES; t += n_warps_total) {
        int pf = t + (DEPTH - 1) * n_warps_total;
        int ps = slot + (DEPTH - 1);
        if (ps >= DEPTH) ps -= DEPTH;
        if (pf < NUM_TILES)
            issue_tile_load(dsts[ps], pred, pf, lane);
        asm volatile("cp.async.commit_group;");      // may be an empty group
        asm volatile("cp.async.wait_group %0;" :: "n"(DEPTH - 1));
        __syncwarp();

        compute_tile(wbase + slot * TILE_FLOATS, out, t, lane);

        if (++slot == DEPTH) slot = 0;
    }
}

extern "C" void kernel_launch(void* const* d_in, const int* in_sizes, int n_in,
                              void* d_out, int out_size)
{
    const float* pred = (const float*)d_in[0];
    // d_in[1] = score_threshold — unused by the reference computation.
    float* out = (float*)d_out;

    cudaFuncSetAttribute(yolo_decode_kernel,
                         cudaFuncAttributeMaxDynamicSharedMemorySize,
                         SMEM_BYTES);

    const int blocks = 296;                        // 2 per SM, persistent
    const int n_warps = blocks * WARPS_PER_BLOCK;  // 1776
    yolo_decode_kernel<<<blocks, THREADS, SMEM_BYTES>>>(pred, out, n_warps);
}